// round 2
// baseline (speedup 1.0000x reference)
#include <cuda_runtime.h>

// ---------------------------------------------------------------------------
// RLFrameSelector: B=32, T=2048, F=512, U=128, k=64
//   mask  = any(x != 0, axis=-1)
//   h     = relu(x @ W1 + b1)        [B,T,128]
//   s     = h @ W2 + b2              [B,T]
//   s     = mask ? s : -1e9
//   sel   = top-64 frames per row
//   out   = x * sel
// ---------------------------------------------------------------------------

#define B_   32
#define T_   2048
#define F_   512
#define U_   128
#define K_   64
#define NFRAMES (B_ * T_)        // 65536
#define NEG_BIG_F (-1.0e9f)

static __device__ float         g_scores[NFRAMES];
static __device__ unsigned char g_sel[NFRAMES];

// ---- packed f32x2 helpers (sm_100+ only; ptxas never auto-fuses these) ----
__device__ __forceinline__ unsigned long long pack2(float lo, float hi) {
    unsigned long long r;
    asm("mov.b64 %0, {%1, %2};" : "=l"(r) : "f"(lo), "f"(hi));
    return r;
}
__device__ __forceinline__ void unpack2(unsigned long long v, float& lo, float& hi) {
    asm("mov.b64 {%0, %1}, %2;" : "=f"(lo), "=f"(hi) : "l"(v));
}
__device__ __forceinline__ void ffma2(unsigned long long& d,
                                      unsigned long long a, unsigned long long b) {
    // d = a * b + d   (elementwise on two packed f32)
    asm("fma.rn.f32x2 %0, %1, %2, %0;" : "+l"(d) : "l"(a), "l"(b));
}
__device__ __forceinline__ void fadd2(unsigned long long& d, unsigned long long a) {
    asm("add.rn.f32x2 %0, %1, %2;" : "=l"(d) : "l"(d), "l"(a));
}

// ---------------------------------------------------------------------------
// Pass 1: fused scoring GEMM.
// Block tile: 64 frames x 128 u, K staged by 16, double-buffered smem.
// 256 threads: u_tid = tid&31 owns u = 4*u_tid..+3 ; fr_tid = tid>>5 owns
// frames fr_tid*8..+7 (as 4 f32x2 pairs). 16 FFMA2 per k per thread.
// Epilogue: relu, *W2, warp-shuffle reduce over the 32 u-threads (one warp),
// mask via smem nonzero flags gathered during staging.
// ---------------------------------------------------------------------------
#define KB   16
#define NST  (F_ / KB)     // 32
#define XSTR 66            // padded frame-stride for xs (even -> 8B aligned pairs)

__global__ __launch_bounds__(256) void score_kernel(
    const float* __restrict__ x, const float* __restrict__ W1,
    const float* __restrict__ b1, const float* __restrict__ W2,
    const float* __restrict__ b2)
{
    __shared__ float xs[2][KB][XSTR];     // [k][frame], transposed
    __shared__ float ws[2][KB][U_];       // [k][u]
    __shared__ int   nz[64];

    const int tid    = threadIdx.x;
    const int u_tid  = tid & 31;
    const int fr_tid = tid >> 5;
    const long frame0 = (long)blockIdx.x * 64;

    if (tid < 64) nz[tid] = 0;
    __syncthreads();   // nz zeroed before any nz[lf]=1 write below (race fix)

    // x loader: thread = (frame lf 0..63, quad lq 0..3), one float4/stage
    const int lf = tid >> 2;
    const int lq = tid & 3;
    const float* xg = x + (frame0 + lf) * F_ + lq * 4;

    // w loader: thread loads rows wk and wk+8 of each 16xK stage, one float4 each
    const int wk = tid >> 5;       // 0..7
    const int wu = tid & 31;       // float4 column (u/4)
    const float4* wg = (const float4*)W1;

    unsigned long long acc[4][4];  // [u within 4][frame-pair]
#pragma unroll
    for (int a = 0; a < 4; a++)
#pragma unroll
        for (int p = 0; p < 4; p++) acc[a][p] = 0ull;

    // prefetch + store stage 0
    float4 xr  = *(const float4*)xg;
    float4 wr0 = wg[wk * 32 + wu];
    float4 wr1 = wg[(wk + 8) * 32 + wu];
    {
        xs[0][lq * 4 + 0][lf] = xr.x;
        xs[0][lq * 4 + 1][lf] = xr.y;
        xs[0][lq * 4 + 2][lf] = xr.z;
        xs[0][lq * 4 + 3][lf] = xr.w;
        if (xr.x != 0.f || xr.y != 0.f || xr.z != 0.f || xr.w != 0.f) nz[lf] = 1;
        *(float4*)&ws[0][wk][wu * 4]     = wr0;
        *(float4*)&ws[0][wk + 8][wu * 4] = wr1;
    }
    __syncthreads();

#pragma unroll 1
    for (int s = 0; s < NST; s++) {
        const int buf = s & 1;
        if (s + 1 < NST) {
            xr  = *(const float4*)(xg + (s + 1) * KB);
            wr0 = wg[((s + 1) * KB + wk) * 32 + wu];
            wr1 = wg[((s + 1) * KB + wk + 8) * 32 + wu];
        }
#pragma unroll
        for (int k = 0; k < KB; k++) {
            float4 w4 = *(const float4*)&ws[buf][k][u_tid * 4];
            const float* xrow = &xs[buf][k][fr_tid * 8];
            unsigned long long xp0 = *(const unsigned long long*)(xrow + 0);
            unsigned long long xp1 = *(const unsigned long long*)(xrow + 2);
            unsigned long long xp2 = *(const unsigned long long*)(xrow + 4);
            unsigned long long xp3 = *(const unsigned long long*)(xrow + 6);
            unsigned long long wp;
            wp = pack2(w4.x, w4.x);
            ffma2(acc[0][0], xp0, wp); ffma2(acc[0][1], xp1, wp);
            ffma2(acc[0][2], xp2, wp); ffma2(acc[0][3], xp3, wp);
            wp = pack2(w4.y, w4.y);
            ffma2(acc[1][0], xp0, wp); ffma2(acc[1][1], xp1, wp);
            ffma2(acc[1][2], xp2, wp); ffma2(acc[1][3], xp3, wp);
            wp = pack2(w4.z, w4.z);
            ffma2(acc[2][0], xp0, wp); ffma2(acc[2][1], xp1, wp);
            ffma2(acc[2][2], xp2, wp); ffma2(acc[2][3], xp3, wp);
            wp = pack2(w4.w, w4.w);
            ffma2(acc[3][0], xp0, wp); ffma2(acc[3][1], xp1, wp);
            ffma2(acc[3][2], xp2, wp); ffma2(acc[3][3], xp3, wp);
        }
        if (s + 1 < NST) {
            const int nb = buf ^ 1;
            xs[nb][lq * 4 + 0][lf] = xr.x;
            xs[nb][lq * 4 + 1][lf] = xr.y;
            xs[nb][lq * 4 + 2][lf] = xr.z;
            xs[nb][lq * 4 + 3][lf] = xr.w;
            if (xr.x != 0.f || xr.y != 0.f || xr.z != 0.f || xr.w != 0.f) nz[lf] = 1;
            *(float4*)&ws[nb][wk][wu * 4]     = wr0;
            *(float4*)&ws[nb][wk + 8][wu * 4] = wr1;
        }
        __syncthreads();
    }

    // ---- epilogue: +b1, relu, *W2, reduce over u (one warp per frame group)
    float4 bb = *(const float4*)(b1 + u_tid * 4);
    float4 v2 = *(const float4*)(W2 + u_tid * 4);
    const float beta = b2[0];

    unsigned long long part[4] = {0ull, 0ull, 0ull, 0ull};
    {
        const float bArr[4] = {bb.x, bb.y, bb.z, bb.w};
        const float wArr[4] = {v2.x, v2.y, v2.z, v2.w};
#pragma unroll
        for (int a = 0; a < 4; a++) {
            unsigned long long bp = pack2(bArr[a], bArr[a]);
            unsigned long long wp = pack2(wArr[a], wArr[a]);
#pragma unroll
            for (int p = 0; p < 4; p++) {
                unsigned long long h = acc[a][p];
                fadd2(h, bp);
                float lo, hi; unpack2(h, lo, hi);
                lo = fmaxf(lo, 0.f); hi = fmaxf(hi, 0.f);
                h = pack2(lo, hi);
                ffma2(part[p], h, wp);
            }
        }
    }
#pragma unroll
    for (int off = 16; off > 0; off >>= 1) {
#pragma unroll
        for (int p = 0; p < 4; p++) {
            unsigned long long o = __shfl_down_sync(0xffffffffu, part[p], off);
            fadd2(part[p], o);
        }
    }
    if (u_tid == 0) {
#pragma unroll
        for (int p = 0; p < 4; p++) {
            float lo, hi; unpack2(part[p], lo, hi);
            const int f0 = fr_tid * 8 + 2 * p;
            g_scores[frame0 + f0]     = nz[f0]     ? (lo + beta) : NEG_BIG_F;
            g_scores[frame0 + f0 + 1] = nz[f0 + 1] ? (hi + beta) : NEG_BIG_F;
        }
    }
}

// ---------------------------------------------------------------------------
// Pass 2: per-row top-64 via 64x iterative argmax. Key = (sortable score, 2047-idx)
// so ties prefer the lower index (matches stable lax.top_k).
// ---------------------------------------------------------------------------
__global__ __launch_bounds__(256) void topk_kernel()
{
    __shared__ float s[T_];
    __shared__ unsigned long long red[8];
    const int row = blockIdx.x;
    const int tid = threadIdx.x;
    const float* sc = g_scores + row * T_;

    for (int i = tid; i < T_; i += 256) s[i] = sc[i];
    for (int i = tid; i < T_; i += 256) g_sel[row * T_ + i] = 0;
    __syncthreads();

    for (int it = 0; it < K_; it++) {
        unsigned long long best = 0ull;
#pragma unroll
        for (int j = 0; j < T_ / 256; j++) {
            const int i = tid + j * 256;
            const float v = s[i];
            unsigned u = __float_as_uint(v);
            u = (u & 0x80000000u) ? ~u : (u | 0x80000000u);  // monotone map
            const unsigned long long key =
                ((unsigned long long)u << 32) | (unsigned)(T_ - 1 - i);
            if (key > best) best = key;
        }
#pragma unroll
        for (int off = 16; off > 0; off >>= 1) {
            unsigned long long o = __shfl_down_sync(0xffffffffu, best, off);
            if (o > best) best = o;
        }
        if ((tid & 31) == 0) red[tid >> 5] = best;
        __syncthreads();
        if (tid == 0) {
            unsigned long long b = red[0];
#pragma unroll
            for (int w = 1; w < 8; w++) if (red[w] > b) b = red[w];
            const int idx = (T_ - 1) - (int)(b & 0xffffffffu);
            g_sel[row * T_ + idx] = 1;
            s[idx] = -__int_as_float(0x7f800000);  // -inf: never re-selected
        }
        __syncthreads();
    }
}

// ---------------------------------------------------------------------------
// Pass 3: out = sel ? x : 0, float4-vectorized. Reads x only for kept frames.
// ---------------------------------------------------------------------------
__global__ __launch_bounds__(256) void output_kernel(
    const float4* __restrict__ x4, float4* __restrict__ out4)
{
    const long gid = (long)blockIdx.x * 256 + threadIdx.x;  // one float4 each
    const int frame = (int)(gid >> 7);                       // 128 float4 / frame
    float4 v = make_float4(0.f, 0.f, 0.f, 0.f);
    if (g_sel[frame]) v = x4[gid];
    out4[gid] = v;
}

// ---------------------------------------------------------------------------
extern "C" void kernel_launch(void* const* d_in, const int* in_sizes, int n_in,
                              void* d_out, int out_size)
{
    const float* x  = (const float*)d_in[0];
    const float* W1 = (const float*)d_in[1];
    const float* b1 = (const float*)d_in[2];
    const float* W2 = (const float*)d_in[3];
    const float* b2 = (const float*)d_in[4];
    // d_in[5] is k (fixed at 64 by the problem spec; device scalar not
    // host-readable under graph capture)

    score_kernel<<<NFRAMES / 64, 256>>>(x, W1, b1, W2, b2);
    topk_kernel<<<B_, 256>>>();
    const int n4 = out_size / 4;
    output_kernel<<<n4 / 256, 256>>>((const float4*)x, (float4*)d_out);
}